// round 11
// baseline (speedup 1.0000x reference)
#include <cuda_runtime.h>
#include <cuda_bf16.h>
#include <math.h>

// Problem dims (fixed)
#define LSEQ 128
#define BATCH 1024
#define H 256
#define D 512          // 2*H
#define G3 1536        // 3*D
#define ODE_H 128
#define IN_U 32
#define OUT_DIM 16
#define M_TOT (LSEQ * BATCH)   // 131072

#define ROWS 8                 // batch rows per CTA in sequential kernel

// ---------------- device scratch (no cudaMalloc allowed) ----------------
__device__ float g_X[(size_t)M_TOT * D];       // 268 MB  embedded inputs
__device__ float g_GI[(size_t)M_TOT * G3];     // 805 MB  precomputed gi
__device__ float g_HS[(size_t)M_TOT * D];      // 268 MB  h_seq (pre-step states)
__device__ float g_WihT[D * G3];               // 3 MB    W_ih^T  [k][c]
__device__ float g_WhhT[D * G3];               // 3 MB    W_hh^T  [k][c]

// ---------------- kernel 0: transpose weights ----------------
__global__ __launch_bounds__(256) void transpose_w(
    const float* __restrict__ Wih, const float* __restrict__ Whh) {
  int idx = blockIdx.x * 256 + threadIdx.x;
  if (idx < D * G3) {
    int k = idx / G3;
    int c = idx - k * G3;
    g_WihT[idx] = Wih[c * D + k];
    g_WhhT[idx] = Whh[c * D + k];
  }
}

// ---------------- kernel 1: input embeddings -> X ----------------
// X[i][0:256]   = tanh(ext[i][:32] @ Wu + bu)
// X[i][256:512] = tanh(obs[i]      @ Wx + bx)
__global__ __launch_bounds__(256) void embed_kernel(
    const float* __restrict__ ext, const float* __restrict__ obs,
    const float* __restrict__ Wu, const float* __restrict__ bu,
    const float* __restrict__ Wx, const float* __restrict__ bx) {
  __shared__ float es[8 * 33];
  __shared__ float os[8 * 16];
  int i0 = blockIdx.x * 8;
  int tid = threadIdx.x;
  for (int idx = tid; idx < 8 * 33; idx += 256) es[idx] = ext[(size_t)i0 * 33 + idx];
  for (int idx = tid; idx < 8 * 16; idx += 256) os[idx] = obs[(size_t)i0 * 16 + idx];
  __syncthreads();
  int h = tid;  // 0..255
  float aU[8], aX[8];
  float bU = bu[h], bX = bx[h];
#pragma unroll
  for (int r = 0; r < 8; r++) { aU[r] = bU; aX[r] = bX; }
#pragma unroll 4
  for (int j = 0; j < IN_U; j++) {
    float w = Wu[j * H + h];
#pragma unroll
    for (int r = 0; r < 8; r++) aU[r] += es[r * 33 + j] * w;
  }
#pragma unroll 4
  for (int j = 0; j < OUT_DIM; j++) {
    float w = Wx[j * H + h];
#pragma unroll
    for (int r = 0; r < 8; r++) aX[r] += os[r * 16 + j] * w;
  }
#pragma unroll
  for (int r = 0; r < 8; r++) {
    size_t row = (size_t)(i0 + r) * D;
    g_X[row + h]     = tanhf(aU[r]);
    g_X[row + H + h] = tanhf(aX[r]);
  }
}

// ---------------- kernel 2: GI = X @ WihT + b_ih  (M=131072, N=1536, K=512) ----------------
// Classic 128x128x8 double-buffered SIMT sgemm, 256 threads, 8x8 micro-tile.
__global__ __launch_bounds__(256) void gemm_gi(const float* __restrict__ b_ih) {
  __shared__ float As[2][8][128];
  __shared__ float Bs[2][8][128];
  const int tid = threadIdx.x;
  const int m0 = blockIdx.x * 128;
  const int n0 = blockIdx.y * 128;

  const int arow = tid >> 1, akq = (tid & 1) * 4;
  const int brow = tid >> 5, bcol = (tid & 31) * 4;

  const float* Aptr = g_X + (size_t)(m0 + arow) * D + akq;
  const float* Bptr = g_WihT + (size_t)brow * G3 + n0 + bcol;

  float4 a4 = *(const float4*)Aptr;
  float4 b4 = *(const float4*)Bptr;
  As[0][akq + 0][arow] = a4.x;
  As[0][akq + 1][arow] = a4.y;
  As[0][akq + 2][arow] = a4.z;
  As[0][akq + 3][arow] = a4.w;
  *(float4*)&Bs[0][brow][bcol] = b4;
  __syncthreads();

  float acc[8][8];
#pragma unroll
  for (int i = 0; i < 8; i++)
#pragma unroll
    for (int j = 0; j < 8; j++) acc[i][j] = 0.f;

  const int tx = tid & 15, ty = tid >> 4;

  for (int kt = 0; kt < 64; kt++) {
    const int cur = kt & 1;
    float4 an, bn;
    if (kt < 63) {
      an = *(const float4*)(Aptr + (kt + 1) * 8);
      bn = *(const float4*)(Bptr + (size_t)(kt + 1) * 8 * G3);
    }
#pragma unroll
    for (int k = 0; k < 8; k++) {
      float4 arl = *(const float4*)&As[cur][k][ty * 8];
      float4 arh = *(const float4*)&As[cur][k][ty * 8 + 4];
      float4 brl = *(const float4*)&Bs[cur][k][tx * 8];
      float4 brh = *(const float4*)&Bs[cur][k][tx * 8 + 4];
      float ar[8] = {arl.x, arl.y, arl.z, arl.w, arh.x, arh.y, arh.z, arh.w};
      float br[8] = {brl.x, brl.y, brl.z, brl.w, brh.x, brh.y, brh.z, brh.w};
#pragma unroll
      for (int i = 0; i < 8; i++)
#pragma unroll
        for (int j = 0; j < 8; j++) acc[i][j] += ar[i] * br[j];
    }
    if (kt < 63) {
      const int nxt = cur ^ 1;
      As[nxt][akq + 0][arow] = an.x;
      As[nxt][akq + 1][arow] = an.y;
      As[nxt][akq + 2][arow] = an.z;
      As[nxt][akq + 3][arow] = an.w;
      *(float4*)&Bs[nxt][brow][bcol] = bn;
      __syncthreads();
    }
  }

  float bs[8];
#pragma unroll
  for (int j = 0; j < 8; j++) bs[j] = b_ih[n0 + tx * 8 + j];
#pragma unroll
  for (int i = 0; i < 8; i++) {
    size_t row = (size_t)(m0 + ty * 8 + i) * G3 + n0 + tx * 8;
    float4 lo, hi;
    lo.x = acc[i][0] + bs[0]; lo.y = acc[i][1] + bs[1];
    lo.z = acc[i][2] + bs[2]; lo.w = acc[i][3] + bs[3];
    hi.x = acc[i][4] + bs[4]; hi.y = acc[i][5] + bs[5];
    hi.z = acc[i][6] + bs[6]; hi.w = acc[i][7] + bs[7];
    *(float4*)&g_GI[row]     = lo;
    *(float4*)&g_GI[row + 4] = hi;
  }
}

// ---------------- kernel 3: sequential recurrence ----------------
// grid = 128 CTAs, 256 threads; each CTA owns 8 batch rows for all 128 steps.
__global__ __launch_bounds__(256) void seq_kernel(
    const float* __restrict__ b_hh, const float* __restrict__ W1,
    const float* __restrict__ b1, const float* __restrict__ W2,
    const float* __restrict__ b2, const float* __restrict__ ext) {
  __shared__ float h_s[D * ROWS];       // k-major state  [k][r]   16 KB
  __shared__ float hn_s[ROWS * D];      // row-major state [r][d]  16 KB
  __shared__ float mid_s[ROWS * ODE_H]; // ODE hidden              4 KB
  __shared__ float dt_s[ROWS];

  const int tid = threadIdx.x;
  const int b0 = blockIdx.x * ROWS;

  for (int idx = tid; idx < D * ROWS; idx += 256) { h_s[idx] = 0.f; hn_s[idx] = 0.f; }

  // this thread owns gate columns {2t,2t+1} in each of the 3 gate blocks
  const int dc = 2 * tid;
  float bh[6];
  bh[0] = b_hh[dc];          bh[1] = b_hh[dc + 1];
  bh[2] = b_hh[D + dc];      bh[3] = b_hh[D + dc + 1];
  bh[4] = b_hh[2 * D + dc];  bh[5] = b_hh[2 * D + dc + 1];
  __syncthreads();

  for (int t = 0; t < LSEQ; t++) {
    // --- Phase A: emit pre-step state to HS, load dt ---
    const size_t rowbase = (size_t)(t * BATCH + b0);
    for (int idx = tid; idx < ROWS * D; idx += 256) {
      int r = idx >> 9, d = idx & (D - 1);
      g_HS[(rowbase + r) * D + d] = hn_s[r * D + d];
    }
    if (tid < ROWS) dt_s[tid] = ext[(rowbase + tid) * (IN_U + 1) + IN_U];
    __syncthreads();

    // --- Phase B: gh = h @ Whh^T (+ b_hh), thread-local gate columns ---
    float acc[6][ROWS];
#pragma unroll
    for (int ci = 0; ci < 6; ci++)
#pragma unroll
      for (int r = 0; r < ROWS; r++) acc[ci][r] = bh[ci];

    const float* wp = g_WhhT + dc;
#pragma unroll 2
    for (int k = 0; k < D; k++) {
      const float* wk = wp + (size_t)k * G3;
      float2 wr = *(const float2*)(wk);
      float2 wz = *(const float2*)(wk + D);
      float2 wn = *(const float2*)(wk + 2 * D);
      float4 ha = *(const float4*)(h_s + k * ROWS);
      float4 hb = *(const float4*)(h_s + k * ROWS + 4);
      float hv[8] = {ha.x, ha.y, ha.z, ha.w, hb.x, hb.y, hb.z, hb.w};
#pragma unroll
      for (int r = 0; r < ROWS; r++) {
        acc[0][r] += wr.x * hv[r]; acc[1][r] += wr.y * hv[r];
        acc[2][r] += wz.x * hv[r]; acc[3][r] += wz.y * hv[r];
        acc[4][r] += wn.x * hv[r]; acc[5][r] += wn.y * hv[r];
      }
    }

    // --- Phase C: gates (fused, thread-local) ---
    const float* gib = g_GI + rowbase * G3 + dc;
#pragma unroll
    for (int r = 0; r < ROWS; r++) {
      const float* gr_ = gib + (size_t)r * G3;
      float2 ir = *(const float2*)(gr_);
      float2 iz = *(const float2*)(gr_ + D);
      float2 in_ = *(const float2*)(gr_ + 2 * D);
      float rg0 = 1.f / (1.f + expf(-(ir.x + acc[0][r])));
      float rg1 = 1.f / (1.f + expf(-(ir.y + acc[1][r])));
      float zg0 = 1.f / (1.f + expf(-(iz.x + acc[2][r])));
      float zg1 = 1.f / (1.f + expf(-(iz.y + acc[3][r])));
      float ng0 = tanhf(in_.x + rg0 * acc[4][r]);
      float ng1 = tanhf(in_.y + rg1 * acc[5][r]);
      float hp0 = hn_s[r * D + dc];
      float hp1 = hn_s[r * D + dc + 1];
      hn_s[r * D + dc]     = (1.f - zg0) * ng0 + zg0 * hp0;
      hn_s[r * D + dc + 1] = (1.f - zg1) * ng1 + zg1 * hp1;
    }
    __syncthreads();

    // --- Phase D: mid = tanh(h @ W1 + b1) ---
    {
      int j = tid & (ODE_H - 1);       // 0..127
      int rb = (tid >> 7) * 4;         // 0 or 4
      float a0 = b1[j], a1 = a0, a2 = a0, a3 = a0;
#pragma unroll 4
      for (int k = 0; k < H; k++) {
        float w = W1[k * ODE_H + j];
        a0 += hn_s[(rb + 0) * D + k] * w;
        a1 += hn_s[(rb + 1) * D + k] * w;
        a2 += hn_s[(rb + 2) * D + k] * w;
        a3 += hn_s[(rb + 3) * D + k] * w;
      }
      mid_s[(rb + 0) * ODE_H + j] = tanhf(a0);
      mid_s[(rb + 1) * ODE_H + j] = tanhf(a1);
      mid_s[(rb + 2) * ODE_H + j] = tanhf(a2);
      mid_s[(rb + 3) * ODE_H + j] = tanhf(a3);
    }
    __syncthreads();

    // --- Phase E: f = mid @ W2 + b2 ; h += dt*f  (first H dims only) ---
    {
      int d = tid;  // 0..255 == H
      float a2c[ROWS];
      float bb = b2[d];
#pragma unroll
      for (int r = 0; r < ROWS; r++) a2c[r] = bb;
#pragma unroll 4
      for (int k = 0; k < ODE_H; k++) {
        float w = W2[k * H + d];
#pragma unroll
        for (int r = 0; r < ROWS; r++) a2c[r] += mid_s[r * ODE_H + k] * w;
      }
#pragma unroll
      for (int r = 0; r < ROWS; r++)
        hn_s[r * D + d] += dt_s[r] * a2c[r];
    }
    __syncthreads();

    // --- Phase F: rebuild k-major state for next step ---
    for (int idx = tid; idx < ROWS * D; idx += 256) {
      int r = idx >> 9, d = idx & (D - 1);
      h_s[d * ROWS + r] = hn_s[r * D + d];
    }
    __syncthreads();
  }
}

// ---------------- kernel 4: x_seq = HS @ WLy + bLy ----------------
__global__ __launch_bounds__(256) void out_kernel(
    const float* __restrict__ WLy, const float* __restrict__ bLy,
    float* __restrict__ out) {
  int i0 = blockIdx.x * 16;
  int o = threadIdx.x & 15;
  int r = threadIdx.x >> 4;
  size_t row = (size_t)(i0 + r);
  const float* h = g_HS + row * D;
  float acc = bLy[o];
#pragma unroll 4
  for (int d = 0; d < D; d++) acc += h[d] * WLy[d * OUT_DIM + o];
  out[row * OUT_DIM + o] = acc;
}

// ---------------- launch ----------------
extern "C" void kernel_launch(void* const* d_in, const int* in_sizes, int n_in,
                              void* d_out, int out_size) {
  const float* ext  = (const float*)d_in[0];
  const float* obs  = (const float*)d_in[1];
  const float* Wu   = (const float*)d_in[2];
  const float* bu   = (const float*)d_in[3];
  const float* Wx   = (const float*)d_in[4];
  const float* bx   = (const float*)d_in[5];
  const float* Wih  = (const float*)d_in[6];
  const float* Whh  = (const float*)d_in[7];
  const float* b_ih = (const float*)d_in[8];
  const float* b_hh = (const float*)d_in[9];
  const float* W1   = (const float*)d_in[10];
  const float* b1   = (const float*)d_in[11];
  const float* W2   = (const float*)d_in[12];
  const float* b2   = (const float*)d_in[13];
  const float* WLy  = (const float*)d_in[14];
  const float* bLy  = (const float*)d_in[15];
  float* out = (float*)d_out;

  transpose_w<<<(D * G3 + 255) / 256, 256>>>(Wih, Whh);
  embed_kernel<<<M_TOT / 8, 256>>>(ext, obs, Wu, bu, Wx, bx);
  gemm_gi<<<dim3(M_TOT / 128, G3 / 128), 256>>>(b_ih);
  seq_kernel<<<BATCH / ROWS, 256>>>(b_hh, W1, b1, W2, b2, ext);
  out_kernel<<<M_TOT / 16, 256>>>(WLy, bLy, out);
}

// round 13
// speedup vs baseline: 1.1864x; 1.1864x over previous
#include <cuda_runtime.h>
#include <cuda_bf16.h>
#include <math.h>

// Problem dims (fixed)
#define LSEQ 128
#define BATCH 1024
#define H 256
#define D 512          // 2*H
#define G3 1536        // 3*D
#define ODE_H 128
#define IN_U 32
#define OUT_DIM 16
#define M_TOT (LSEQ * BATCH)   // 131072

#define ROWS 8                 // batch rows per CTA in sequential kernel

typedef unsigned long long u64;

// ---------------- packed f32x2 helpers ----------------
__device__ __forceinline__ u64 fma2(u64 a, u64 b, u64 c) {
  u64 d;
  asm("fma.rn.f32x2 %0, %1, %2, %3;" : "=l"(d) : "l"(a), "l"(b), "l"(c));
  return d;
}
__device__ __forceinline__ u64 pack2(float lo, float hi) {
  u64 d; asm("mov.b64 %0, {%1, %2};" : "=l"(d) : "f"(lo), "f"(hi)); return d;
}
__device__ __forceinline__ float2 unpack2(u64 v) {
  float2 r; asm("mov.b64 {%0, %1}, %2;" : "=f"(r.x), "=f"(r.y) : "l"(v)); return r;
}

// Exact transcendentals (R11 numerics — do NOT substitute __expf/2-over-1+exp forms:
// tanh via exp has catastrophic cancellation near 0 and compounds over 128 steps)
__device__ __forceinline__ float sig_f(float x) {
  return 1.f / (1.f + expf(-x));
}

// ---------------- device scratch (no cudaMalloc allowed) ----------------
__device__ float g_X[(size_t)M_TOT * D];       // 268 MB  embedded inputs
__device__ float g_GI[(size_t)M_TOT * G3];     // 805 MB  precomputed gi
__device__ float g_HS[(size_t)M_TOT * D];      // 268 MB  h_seq (pre-step states)
__device__ float g_WihT[D * G3];               // 3 MB    W_ih^T  [k][c]
__device__ float g_WhhT[D * G3];               // 3 MB    W_hh^T  [k][c]

// ---------------- kernel 0: transpose weights ----------------
__global__ __launch_bounds__(256) void transpose_w(
    const float* __restrict__ Wih, const float* __restrict__ Whh) {
  int idx = blockIdx.x * 256 + threadIdx.x;
  if (idx < D * G3) {
    int k = idx / G3;
    int c = idx - k * G3;
    g_WihT[idx] = Wih[c * D + k];
    g_WhhT[idx] = Whh[c * D + k];
  }
}

// ---------------- kernel 1: input embeddings -> X ----------------
__global__ __launch_bounds__(256) void embed_kernel(
    const float* __restrict__ ext, const float* __restrict__ obs,
    const float* __restrict__ Wu, const float* __restrict__ bu,
    const float* __restrict__ Wx, const float* __restrict__ bx) {
  __shared__ float es[8 * 33];
  __shared__ float os[8 * 16];
  int i0 = blockIdx.x * 8;
  int tid = threadIdx.x;
  for (int idx = tid; idx < 8 * 33; idx += 256) es[idx] = ext[(size_t)i0 * 33 + idx];
  for (int idx = tid; idx < 8 * 16; idx += 256) os[idx] = obs[(size_t)i0 * 16 + idx];
  __syncthreads();
  int h = tid;
  float aU[8], aX[8];
  float bU = bu[h], bX = bx[h];
#pragma unroll
  for (int r = 0; r < 8; r++) { aU[r] = bU; aX[r] = bX; }
#pragma unroll 4
  for (int j = 0; j < IN_U; j++) {
    float w = Wu[j * H + h];
#pragma unroll
    for (int r = 0; r < 8; r++) aU[r] += es[r * 33 + j] * w;
  }
#pragma unroll 4
  for (int j = 0; j < OUT_DIM; j++) {
    float w = Wx[j * H + h];
#pragma unroll
    for (int r = 0; r < 8; r++) aX[r] += os[r * 16 + j] * w;
  }
#pragma unroll
  for (int r = 0; r < 8; r++) {
    size_t row = (size_t)(i0 + r) * D;
    g_X[row + h]     = tanhf(aU[r]);
    g_X[row + H + h] = tanhf(aX[r]);
  }
}

// ---------------- kernel 2: GI = X @ WihT + b_ih (f32x2 inner product) ----------------
__global__ __launch_bounds__(256) void gemm_gi(const float* __restrict__ b_ih) {
  __shared__ float As[2][8][128];
  __shared__ float Bs[2][8][128];
  const int tid = threadIdx.x;
  const int m0 = blockIdx.x * 128;
  const int n0 = blockIdx.y * 128;

  const int arow = tid >> 1, akq = (tid & 1) * 4;
  const int brow = tid >> 5, bcol = (tid & 31) * 4;

  const float* Aptr = g_X + (size_t)(m0 + arow) * D + akq;
  const float* Bptr = g_WihT + (size_t)brow * G3 + n0 + bcol;

  float4 a4 = *(const float4*)Aptr;
  float4 b4 = *(const float4*)Bptr;
  As[0][akq + 0][arow] = a4.x;
  As[0][akq + 1][arow] = a4.y;
  As[0][akq + 2][arow] = a4.z;
  As[0][akq + 3][arow] = a4.w;
  *(float4*)&Bs[0][brow][bcol] = b4;
  __syncthreads();

  u64 acc2[8][4];
#pragma unroll
  for (int i = 0; i < 8; i++)
#pragma unroll
    for (int j = 0; j < 4; j++) acc2[i][j] = 0ull;

  const int tx = tid & 15, ty = tid >> 4;

  for (int kt = 0; kt < 64; kt++) {
    const int cur = kt & 1;
    float4 an, bn;
    if (kt < 63) {
      an = *(const float4*)(Aptr + (kt + 1) * 8);
      bn = *(const float4*)(Bptr + (size_t)(kt + 1) * 8 * G3);
    }
#pragma unroll
    for (int k = 0; k < 8; k++) {
      float4 arl = *(const float4*)&As[cur][k][ty * 8];
      float4 arh = *(const float4*)&As[cur][k][ty * 8 + 4];
      ulonglong2 bl = *(const ulonglong2*)&Bs[cur][k][tx * 8];
      ulonglong2 bh = *(const ulonglong2*)&Bs[cur][k][tx * 8 + 4];
      u64 bp[4] = {bl.x, bl.y, bh.x, bh.y};
      float ar[8] = {arl.x, arl.y, arl.z, arl.w, arh.x, arh.y, arh.z, arh.w};
#pragma unroll
      for (int i = 0; i < 8; i++) {
        u64 ai = pack2(ar[i], ar[i]);
#pragma unroll
        for (int j = 0; j < 4; j++) acc2[i][j] = fma2(ai, bp[j], acc2[i][j]);
      }
    }
    if (kt < 63) {
      const int nxt = cur ^ 1;
      As[nxt][akq + 0][arow] = an.x;
      As[nxt][akq + 1][arow] = an.y;
      As[nxt][akq + 2][arow] = an.z;
      As[nxt][akq + 3][arow] = an.w;
      *(float4*)&Bs[nxt][brow][bcol] = bn;
      __syncthreads();
    }
  }

  float bs[8];
#pragma unroll
  for (int j = 0; j < 8; j++) bs[j] = b_ih[n0 + tx * 8 + j];
#pragma unroll
  for (int i = 0; i < 8; i++) {
    float2 v0 = unpack2(acc2[i][0]);
    float2 v1 = unpack2(acc2[i][1]);
    float2 v2 = unpack2(acc2[i][2]);
    float2 v3 = unpack2(acc2[i][3]);
    size_t row = (size_t)(m0 + ty * 8 + i) * G3 + n0 + tx * 8;
    float4 lo, hi;
    lo.x = v0.x + bs[0]; lo.y = v0.y + bs[1];
    lo.z = v1.x + bs[2]; lo.w = v1.y + bs[3];
    hi.x = v2.x + bs[4]; hi.y = v2.y + bs[5];
    hi.z = v3.x + bs[6]; hi.w = v3.y + bs[7];
    *(float4*)&g_GI[row]     = lo;
    *(float4*)&g_GI[row + 4] = hi;
  }
}

// ---------------- kernel 3: sequential recurrence (512 threads, f32x2) ----------------
// grid = 128 CTAs, 512 threads; each CTA owns 8 batch rows for all 128 steps.
// Thread c (=tid) owns gate column c of the r/z/n blocks.
// State packed across batch rows: h_s k-major [k][8] -> u64 row pairs.
__global__ __launch_bounds__(512) void seq_kernel(
    const float* __restrict__ b_hh, const float* __restrict__ W1,
    const float* __restrict__ b1, const float* __restrict__ W2,
    const float* __restrict__ b2, const float* __restrict__ ext) {
  __shared__ float h_s[D * ROWS];        // k-major state  [k][r]   16 KB
  __shared__ float hn_s[ROWS * D];       // row-major state [r][d]  16 KB
  __shared__ float mid_s[ODE_H * ROWS];  // ODE hidden k-major [j][r] 4 KB
  __shared__ float dt_s[ROWS];

  const int tid = threadIdx.x;
  const int b0 = blockIdx.x * ROWS;
  const int c = tid;                     // 0..511

  for (int idx = tid; idx < D * ROWS; idx += 512) { h_s[idx] = 0.f; hn_s[idx] = 0.f; }

  const u64 bR2 = pack2(b_hh[c], b_hh[c]);
  const u64 bZ2 = pack2(b_hh[D + c], b_hh[D + c]);
  const u64 bN2 = pack2(b_hh[2 * D + c], b_hh[2 * D + c]);
  __syncthreads();

  for (int t = 0; t < LSEQ; t++) {
    const size_t rowbase = (size_t)(t * BATCH + b0);

    // --- Phase A: emit pre-step state to HS, load dt ---
    {
      const float4* src = (const float4*)hn_s;
      for (int idx = tid; idx < ROWS * D / 4; idx += 512) {
        int r = idx >> 7, q = idx & 127;
        ((float4*)(g_HS + (rowbase + r) * D))[q] = src[idx];
      }
      if (tid < ROWS) dt_s[tid] = ext[(rowbase + tid) * (IN_U + 1) + IN_U];
    }
    __syncthreads();

    // --- Phase B: gh = h @ Whh^T (+b_hh), f32x2 packed across row pairs ---
    u64 accR[4], accZ[4], accN[4];
#pragma unroll
    for (int p = 0; p < 4; p++) { accR[p] = bR2; accZ[p] = bZ2; accN[p] = bN2; }

    const float* wpR = g_WhhT + c;
    const float* wpZ = g_WhhT + D + c;
    const float* wpN = g_WhhT + 2 * D + c;
#pragma unroll 4
    for (int k = 0; k < D; k++) {
      float wr = __ldg(wpR + (size_t)k * G3);
      float wz = __ldg(wpZ + (size_t)k * G3);
      float wn = __ldg(wpN + (size_t)k * G3);
      u64 wr2 = pack2(wr, wr), wz2 = pack2(wz, wz), wn2 = pack2(wn, wn);
      ulonglong2 ha = *(const ulonglong2*)(h_s + k * ROWS);
      ulonglong2 hb = *(const ulonglong2*)(h_s + k * ROWS + 4);
      u64 hp[4] = {ha.x, ha.y, hb.x, hb.y};
#pragma unroll
      for (int p = 0; p < 4; p++) {
        accR[p] = fma2(wr2, hp[p], accR[p]);
        accZ[p] = fma2(wz2, hp[p], accZ[p]);
        accN[p] = fma2(wn2, hp[p], accN[p]);
      }
    }

    // --- Phase C: gates (thread-local column). Write hn_s (own column, safe);
    //     stash v and defer the h_s publish until after a barrier — other warps
    //     may still be reading h_s in Phase B. ---
    float vout[ROWS];
    {
      const float* gib = g_GI + rowbase * G3 + c;
#pragma unroll
      for (int p = 0; p < 4; p++) {
        float2 aR = unpack2(accR[p]);
        float2 aZ = unpack2(accZ[p]);
        float2 aN = unpack2(accN[p]);
#pragma unroll
        for (int s = 0; s < 2; s++) {
          int r = 2 * p + s;
          const float* gr_ = gib + (size_t)r * G3;
          float ir = gr_[0], iz = gr_[D], inn = gr_[2 * D];
          float ga = s ? aR.y : aR.x;
          float gz = s ? aZ.y : aZ.x;
          float gn = s ? aN.y : aN.x;
          float rg = sig_f(ir + ga);
          float zg = sig_f(iz + gz);
          float ng = tanhf(inn + rg * gn);
          float hp0 = hn_s[r * D + c];
          float v = (1.f - zg) * ng + zg * hp0;
          hn_s[r * D + c] = v;
          vout[r] = v;
        }
      }
    }
    __syncthreads();

    // --- Phase C2: publish c-half (c >= H) of k-major state; ODE won't touch it ---
    if (c >= H) {
#pragma unroll
      for (int r = 0; r < ROWS; r++) h_s[c * ROWS + r] = vout[r];
    }

    // --- Phase D: mid = tanh(h @ W1 + b1), 2 rows/thread packed ---
    {
      int j = tid & (ODE_H - 1);
      int rb = (tid >> 7) * 2;            // rows rb, rb+1
      float bb = b1[j];
      u64 acc = pack2(bb, bb);
      const float* h0 = hn_s + rb * D;
      const float* h1 = hn_s + (rb + 1) * D;
#pragma unroll 4
      for (int k = 0; k < H; k++) {
        float w = W1[k * ODE_H + j];
        u64 hv = pack2(h0[k], h1[k]);
        acc = fma2(pack2(w, w), hv, acc);
      }
      float2 v = unpack2(acc);
      u64 outp = pack2(tanhf(v.x), tanhf(v.y));
      *(u64*)&mid_s[j * ROWS + rb] = outp;
    }
    __syncthreads();

    // --- Phase E: f = mid @ W2 + b2 ; h += dt*f (first H dims), 4 rows/thread ---
    {
      int d = tid & (H - 1);
      int rb = (tid >> 8) * 4;            // rows rb..rb+3
      float bb = b2[d];
      u64 acc0 = pack2(bb, bb), acc1 = acc0;
#pragma unroll 4
      for (int k = 0; k < ODE_H; k++) {
        float w = W2[k * H + d];
        u64 w2 = pack2(w, w);
        ulonglong2 mv = *(const ulonglong2*)(mid_s + k * ROWS + rb);
        acc0 = fma2(w2, mv.x, acc0);
        acc1 = fma2(w2, mv.y, acc1);
      }
      float2 f01 = unpack2(acc0);
      float2 f23 = unpack2(acc1);
      float fv[4] = {f01.x, f01.y, f23.x, f23.y};
#pragma unroll
      for (int s = 0; s < 4; s++) {
        int r = rb + s;
        float v = hn_s[r * D + d] + dt_s[r] * fv[s];
        hn_s[r * D + d] = v;
        h_s[d * ROWS + r] = v;            // d < H half final now
      }
    }
    __syncthreads();
  }
}

// ---------------- kernel 4: x_seq = HS @ WLy + bLy ----------------
__global__ __launch_bounds__(256) void out_kernel(
    const float* __restrict__ WLy, const float* __restrict__ bLy,
    float* __restrict__ out) {
  int i0 = blockIdx.x * 16;
  int o = threadIdx.x & 15;
  int r = threadIdx.x >> 4;
  size_t row = (size_t)(i0 + r);
  const float* h = g_HS + row * D;
  float acc = bLy[o];
#pragma unroll 4
  for (int d = 0; d < D; d++) acc += h[d] * WLy[d * OUT_DIM + o];
  out[row * OUT_DIM + o] = acc;
}

// ---------------- launch ----------------
extern "C" void kernel_launch(void* const* d_in, const int* in_sizes, int n_in,
                              void* d_out, int out_size) {
  const float* ext  = (const float*)d_in[0];
  const float* obs  = (const float*)d_in[1];
  const float* Wu   = (const float*)d_in[2];
  const float* bu   = (const float*)d_in[3];
  const float* Wx   = (const float*)d_in[4];
  const float* bx   = (const float*)d_in[5];
  const float* Wih  = (const float*)d_in[6];
  const float* Whh  = (const float*)d_in[7];
  const float* b_ih = (const float*)d_in[8];
  const float* b_hh = (const float*)d_in[9];
  const float* W1   = (const float*)d_in[10];
  const float* b1   = (const float*)d_in[11];
  const float* W2   = (const float*)d_in[12];
  const float* b2   = (const float*)d_in[13];
  const float* WLy  = (const float*)d_in[14];
  const float* bLy  = (const float*)d_in[15];
  float* out = (float*)d_out;

  transpose_w<<<(D * G3 + 255) / 256, 256>>>(Wih, Whh);
  embed_kernel<<<M_TOT / 8, 256>>>(ext, obs, Wu, bu, Wx, bx);
  gemm_gi<<<dim3(M_TOT / 128, G3 / 128), 256>>>(b_ih);
  seq_kernel<<<BATCH / ROWS, 512>>>(b_hh, W1, b1, W2, b2, ext);
  out_kernel<<<M_TOT / 16, 256>>>(WLy, bLy, out);
}

// round 15
// speedup vs baseline: 1.4872x; 1.2535x over previous
#include <cuda_runtime.h>
#include <cuda_bf16.h>
#include <math.h>

// Problem dims (fixed)
#define LSEQ 128
#define BATCH 1024
#define H 256
#define D 512          // 2*H
#define G3 1536        // 3*D
#define ODE_H 128
#define IN_U 32
#define OUT_DIM 16
#define M_TOT (LSEQ * BATCH)   // 131072

#define ROWS 8                 // batch rows per CTA in sequential kernel

typedef unsigned long long u64;

// ---------------- packed f32x2 helpers ----------------
__device__ __forceinline__ u64 fma2(u64 a, u64 b, u64 c) {
  u64 d;
  asm("fma.rn.f32x2 %0, %1, %2, %3;" : "=l"(d) : "l"(a), "l"(b), "l"(c));
  return d;
}
__device__ __forceinline__ u64 pack2(float lo, float hi) {
  u64 d; asm("mov.b64 %0, {%1, %2};" : "=l"(d) : "f"(lo), "f"(hi)); return d;
}
__device__ __forceinline__ float2 unpack2(u64 v) {
  float2 r; asm("mov.b64 {%0, %1}, %2;" : "=f"(r.x), "=f"(r.y) : "l"(v)); return r;
}

// Exact transcendentals (proven 5.7e-7 numerics — do NOT substitute __expf forms)
__device__ __forceinline__ float sig_f(float x) {
  return 1.f / (1.f + expf(-x));
}

// ---------------- device scratch (no cudaMalloc allowed) ----------------
__device__ float g_X[(size_t)M_TOT * D];       // 268 MB  embedded inputs
__device__ float g_GI[(size_t)M_TOT * G3];     // 805 MB  precomputed gi
__device__ float g_HS[(size_t)M_TOT * D];      // 268 MB  h_seq (pre-step states)
__device__ float g_WihT[D * G3];               // 3 MB    W_ih^T  [k][c]
__device__ float g_WhhT[D * G3];               // 3 MB    W_hh^T  [k][c]

// ---------------- kernel 0: transpose weights ----------------
__global__ __launch_bounds__(256) void transpose_w(
    const float* __restrict__ Wih, const float* __restrict__ Whh) {
  int idx = blockIdx.x * 256 + threadIdx.x;
  if (idx < D * G3) {
    int k = idx / G3;
    int c = idx - k * G3;
    g_WihT[idx] = Wih[c * D + k];
    g_WhhT[idx] = Whh[c * D + k];
  }
}

// ---------------- kernel 1: input embeddings -> X ----------------
__global__ __launch_bounds__(256) void embed_kernel(
    const float* __restrict__ ext, const float* __restrict__ obs,
    const float* __restrict__ Wu, const float* __restrict__ bu,
    const float* __restrict__ Wx, const float* __restrict__ bx) {
  __shared__ float es[8 * 33];
  __shared__ float os[8 * 16];
  int i0 = blockIdx.x * 8;
  int tid = threadIdx.x;
  for (int idx = tid; idx < 8 * 33; idx += 256) es[idx] = ext[(size_t)i0 * 33 + idx];
  for (int idx = tid; idx < 8 * 16; idx += 256) os[idx] = obs[(size_t)i0 * 16 + idx];
  __syncthreads();
  int h = tid;
  float aU[8], aX[8];
  float bU = bu[h], bX = bx[h];
#pragma unroll
  for (int r = 0; r < 8; r++) { aU[r] = bU; aX[r] = bX; }
#pragma unroll 4
  for (int j = 0; j < IN_U; j++) {
    float w = Wu[j * H + h];
#pragma unroll
    for (int r = 0; r < 8; r++) aU[r] += es[r * 33 + j] * w;
  }
#pragma unroll 4
  for (int j = 0; j < OUT_DIM; j++) {
    float w = Wx[j * H + h];
#pragma unroll
    for (int r = 0; r < 8; r++) aX[r] += os[r * 16 + j] * w;
  }
#pragma unroll
  for (int r = 0; r < 8; r++) {
    size_t row = (size_t)(i0 + r) * D;
    g_X[row + h]     = tanhf(aU[r]);
    g_X[row + H + h] = tanhf(aX[r]);
  }
}

// ---------------- kernel 2: GI = X @ WihT + b_ih (f32x2 inner product) ----------------
__global__ __launch_bounds__(256, 2) void gemm_gi(const float* __restrict__ b_ih) {
  __shared__ float As[2][8][128];
  __shared__ float Bs[2][8][128];
  const int tid = threadIdx.x;
  const int m0 = blockIdx.x * 128;
  const int n0 = blockIdx.y * 128;

  const int arow = tid >> 1, akq = (tid & 1) * 4;
  const int brow = tid >> 5, bcol = (tid & 31) * 4;

  const float* Aptr = g_X + (size_t)(m0 + arow) * D + akq;
  const float* Bptr = g_WihT + (size_t)brow * G3 + n0 + bcol;

  float4 a4 = *(const float4*)Aptr;
  float4 b4 = *(const float4*)Bptr;
  As[0][akq + 0][arow] = a4.x;
  As[0][akq + 1][arow] = a4.y;
  As[0][akq + 2][arow] = a4.z;
  As[0][akq + 3][arow] = a4.w;
  *(float4*)&Bs[0][brow][bcol] = b4;
  __syncthreads();

  u64 acc2[8][4];
#pragma unroll
  for (int i = 0; i < 8; i++)
#pragma unroll
    for (int j = 0; j < 4; j++) acc2[i][j] = 0ull;

  const int tx = tid & 15, ty = tid >> 4;

  for (int kt = 0; kt < 64; kt++) {
    const int cur = kt & 1;
    float4 an, bn;
    if (kt < 63) {
      an = *(const float4*)(Aptr + (kt + 1) * 8);
      bn = *(const float4*)(Bptr + (size_t)(kt + 1) * 8 * G3);
    }
#pragma unroll
    for (int k = 0; k < 8; k++) {
      float4 arl = *(const float4*)&As[cur][k][ty * 8];
      float4 arh = *(const float4*)&As[cur][k][ty * 8 + 4];
      ulonglong2 bl = *(const ulonglong2*)&Bs[cur][k][tx * 8];
      ulonglong2 bh = *(const ulonglong2*)&Bs[cur][k][tx * 8 + 4];
      u64 bp[4] = {bl.x, bl.y, bh.x, bh.y};
      float ar[8] = {arl.x, arl.y, arl.z, arl.w, arh.x, arh.y, arh.z, arh.w};
#pragma unroll
      for (int i = 0; i < 8; i++) {
        u64 ai = pack2(ar[i], ar[i]);
#pragma unroll
        for (int j = 0; j < 4; j++) acc2[i][j] = fma2(ai, bp[j], acc2[i][j]);
      }
    }
    if (kt < 63) {
      const int nxt = cur ^ 1;
      As[nxt][akq + 0][arow] = an.x;
      As[nxt][akq + 1][arow] = an.y;
      As[nxt][akq + 2][arow] = an.z;
      As[nxt][akq + 3][arow] = an.w;
      *(float4*)&Bs[nxt][brow][bcol] = bn;
      __syncthreads();
    }
  }

  float bs[8];
#pragma unroll
  for (int j = 0; j < 8; j++) bs[j] = b_ih[n0 + tx * 8 + j];
#pragma unroll
  for (int i = 0; i < 8; i++) {
    float2 v0 = unpack2(acc2[i][0]);
    float2 v1 = unpack2(acc2[i][1]);
    float2 v2 = unpack2(acc2[i][2]);
    float2 v3 = unpack2(acc2[i][3]);
    size_t row = (size_t)(m0 + ty * 8 + i) * G3 + n0 + tx * 8;
    float4 lo, hi;
    lo.x = v0.x + bs[0]; lo.y = v0.y + bs[1];
    lo.z = v1.x + bs[2]; lo.w = v1.y + bs[3];
    hi.x = v2.x + bs[4]; hi.y = v2.y + bs[5];
    hi.z = v3.x + bs[6]; hi.w = v3.y + bs[7];
    *(float4*)&g_GI[row]     = lo;
    *(float4*)&g_GI[row + 4] = hi;
  }
}

// ---------------- kernel 3: sequential recurrence (512 threads, f32x2) ----------------
// grid = 128 CTAs, 512 threads; each CTA owns 8 batch rows for all 128 steps.
// Thread c owns gate column c of the r/z/n blocks.
// Phase B double-buffers weight loads (24 LDGs in flight) to hide L2 latency.
// h_seq stores merged into Phases C/E (state written for step t+1 from registers).
__global__ __launch_bounds__(512) void seq_kernel(
    const float* __restrict__ b_hh, const float* __restrict__ W1,
    const float* __restrict__ b1, const float* __restrict__ W2,
    const float* __restrict__ b2, const float* __restrict__ ext) {
  __shared__ float h_s[D * ROWS];        // k-major state  [k][r]   16 KB
  __shared__ float hn_s[ROWS * D];       // row-major state [r][d]  16 KB
  __shared__ float mid_s[ODE_H * ROWS];  // ODE hidden k-major [j][r] 4 KB
  __shared__ float dt_s[ROWS];

  const int tid = threadIdx.x;
  const int b0 = blockIdx.x * ROWS;
  const int c = tid;                     // 0..511

  for (int idx = tid; idx < D * ROWS; idx += 512) { h_s[idx] = 0.f; hn_s[idx] = 0.f; }
  // h_seq[0] = 0
  for (int idx = tid; idx < ROWS * D; idx += 512) {
    int r = idx >> 9, d = idx & (D - 1);
    g_HS[(size_t)(b0 + r) * D + d] = 0.f;
  }

  const u64 bR2 = pack2(b_hh[c], b_hh[c]);
  const u64 bZ2 = pack2(b_hh[D + c], b_hh[D + c]);
  const u64 bN2 = pack2(b_hh[2 * D + c], b_hh[2 * D + c]);
  const float* wbase = g_WhhT + c;
  __syncthreads();

  for (int t = 0; t < LSEQ; t++) {
    const size_t rowbase = (size_t)(t * BATCH + b0);
    const bool emit = (t + 1 < LSEQ);

    // dt for this step (read in Phase E, two barriers later)
    if (tid < ROWS) dt_s[tid] = ext[(rowbase + tid) * (IN_U + 1) + IN_U];

    // --- Phase B: gh = h @ Whh^T (+b_hh), double-buffered weight stream ---
    u64 accR[4], accZ[4], accN[4];
#pragma unroll
    for (int p = 0; p < 4; p++) { accR[p] = bR2; accZ[p] = bZ2; accN[p] = bN2; }

    float wA[3][8], wB[3][8];

    auto loadw = [&](int kb, float w[3][8]) {
#pragma unroll
      for (int q = 0; q < 8; q++) {
        const float* wk = wbase + (size_t)(kb + q) * G3;
        w[0][q] = __ldg(wk);
        w[1][q] = __ldg(wk + D);
        w[2][q] = __ldg(wk + 2 * D);
      }
    };
    auto procw = [&](int kb, const float w[3][8]) {
#pragma unroll
      for (int q = 0; q < 8; q++) {
        int k = kb + q;
        ulonglong2 ha = *(const ulonglong2*)(h_s + k * ROWS);
        ulonglong2 hb = *(const ulonglong2*)(h_s + k * ROWS + 4);
        u64 hp[4] = {ha.x, ha.y, hb.x, hb.y};
        u64 wr2 = pack2(w[0][q], w[0][q]);
        u64 wz2 = pack2(w[1][q], w[1][q]);
        u64 wn2 = pack2(w[2][q], w[2][q]);
#pragma unroll
        for (int p = 0; p < 4; p++) {
          accR[p] = fma2(wr2, hp[p], accR[p]);
          accZ[p] = fma2(wz2, hp[p], accZ[p]);
          accN[p] = fma2(wn2, hp[p], accN[p]);
        }
      }
    };

    loadw(0, wA);
    for (int kb = 0; kb < D; kb += 16) {
      loadw(kb + 8, wB);
      procw(kb, wA);
      if (kb + 16 < D) loadw(kb + 16, wA);
      procw(kb + 8, wB);
    }

    // --- Phase C: gates (thread-local column). hn_s write is own-column-safe;
    //     h_s publish deferred past the barrier (other warps still read h_s). ---
    float vout[ROWS];
    {
      const float* gib = g_GI + rowbase * G3 + c;
#pragma unroll
      for (int p = 0; p < 4; p++) {
        float2 aR = unpack2(accR[p]);
        float2 aZ = unpack2(accZ[p]);
        float2 aN = unpack2(accN[p]);
#pragma unroll
        for (int s = 0; s < 2; s++) {
          int r = 2 * p + s;
          const float* gr_ = gib + (size_t)r * G3;
          float ir = gr_[0], iz = gr_[D], inn = gr_[2 * D];
          float ga = s ? aR.y : aR.x;
          float gz = s ? aZ.y : aZ.x;
          float gn = s ? aN.y : aN.x;
          float rg = sig_f(ir + ga);
          float zg = sig_f(iz + gz);
          float ng = tanhf(inn + rg * gn);
          float hp0 = hn_s[r * D + c];
          float v = (1.f - zg) * ng + zg * hp0;
          hn_s[r * D + c] = v;
          vout[r] = v;
          // c-half (untouched by ODE) is final: emit h_seq[t+1] now
          if (emit && c >= H) g_HS[(rowbase + BATCH + r) * D + c] = v;
        }
      }
    }
    __syncthreads();

    // --- Phase C2: publish c-half (c >= H) of k-major state ---
    if (c >= H) {
#pragma unroll
      for (int r = 0; r < ROWS; r++) h_s[c * ROWS + r] = vout[r];
    }

    // --- Phase D: mid = tanh(h @ W1 + b1), 2 rows/thread packed ---
    {
      int j = tid & (ODE_H - 1);
      int rb = (tid >> 7) * 2;            // rows rb, rb+1
      float bb = b1[j];
      u64 acc = pack2(bb, bb);
      const float* h0 = hn_s + rb * D;
      const float* h1 = hn_s + (rb + 1) * D;
#pragma unroll 4
      for (int k = 0; k < H; k++) {
        float w = W1[k * ODE_H + j];
        u64 hv = pack2(h0[k], h1[k]);
        acc = fma2(pack2(w, w), hv, acc);
      }
      float2 v = unpack2(acc);
      u64 outp = pack2(tanhf(v.x), tanhf(v.y));
      *(u64*)&mid_s[j * ROWS + rb] = outp;
    }
    __syncthreads();

    // --- Phase E: f = mid @ W2 + b2 ; h += dt*f (first H dims), 4 rows/thread ---
    {
      int d = tid & (H - 1);
      int rb = (tid >> 8) * 4;            // rows rb..rb+3
      float bb = b2[d];
      u64 acc0 = pack2(bb, bb), acc1 = acc0;
#pragma unroll 4
      for (int k = 0; k < ODE_H; k++) {
        float w = W2[k * H + d];
        u64 w2 = pack2(w, w);
        ulonglong2 mv = *(const ulonglong2*)(mid_s + k * ROWS + rb);
        acc0 = fma2(w2, mv.x, acc0);
        acc1 = fma2(w2, mv.y, acc1);
      }
      float2 f01 = unpack2(acc0);
      float2 f23 = unpack2(acc1);
      float fv[4] = {f01.x, f01.y, f23.x, f23.y};
#pragma unroll
      for (int s = 0; s < 4; s++) {
        int r = rb + s;
        float v = hn_s[r * D + d] + dt_s[r] * fv[s];
        hn_s[r * D + d] = v;
        h_s[d * ROWS + r] = v;            // d < H half final now
        if (emit) g_HS[(rowbase + BATCH + r) * D + d] = v;
      }
    }
    __syncthreads();
  }
}

// ---------------- kernel 4: x_seq = HS @ WLy + bLy ----------------
__global__ __launch_bounds__(256) void out_kernel(
    const float* __restrict__ WLy, const float* __restrict__ bLy,
    float* __restrict__ out) {
  int i0 = blockIdx.x * 16;
  int o = threadIdx.x & 15;
  int r = threadIdx.x >> 4;
  size_t row = (size_t)(i0 + r);
  const float* h = g_HS + row * D;
  float acc = bLy[o];
#pragma unroll 4
  for (int d = 0; d < D; d++) acc += h[d] * WLy[d * OUT_DIM + o];
  out[row * OUT_DIM + o] = acc;
}

// ---------------- launch ----------------
extern "C" void kernel_launch(void* const* d_in, const int* in_sizes, int n_in,
                              void* d_out, int out_size) {
  const float* ext  = (const float*)d_in[0];
  const float* obs  = (const float*)d_in[1];
  const float* Wu   = (const float*)d_in[2];
  const float* bu   = (const float*)d_in[3];
  const float* Wx   = (const float*)d_in[4];
  const float* bx   = (const float*)d_in[5];
  const float* Wih  = (const float*)d_in[6];
  const float* Whh  = (const float*)d_in[7];
  const float* b_ih = (const float*)d_in[8];
  const float* b_hh = (const float*)d_in[9];
  const float* W1   = (const float*)d_in[10];
  const float* b1   = (const float*)d_in[11];
  const float* W2   = (const float*)d_in[12];
  const float* b2   = (const float*)d_in[13];
  const float* WLy  = (const float*)d_in[14];
  const float* bLy  = (const float*)d_in[15];
  float* out = (float*)d_out;

  transpose_w<<<(D * G3 + 255) / 256, 256>>>(Wih, Whh);
  embed_kernel<<<M_TOT / 8, 256>>>(ext, obs, Wu, bu, Wx, bx);
  gemm_gi<<<dim3(M_TOT / 128, G3 / 128), 256>>>(b_ih);
  seq_kernel<<<BATCH / ROWS, 512>>>(b_hh, W1, b1, W2, b2, ext);
  out_kernel<<<M_TOT / 16, 256>>>(WLy, bLy, out);
}